// round 16
// baseline (speedup 1.0000x reference)
#include <cuda_runtime.h>
#include <cuda_fp16.h>
#include <stdint.h>

// SNU on GB300 (base sm_103 ISA — mma.sync HMMA path):
//   out[b,h,t] = spike recurrence over xw[t,b,h] = sum_i x[b,i,t]*W[i,h]
//   B=128, I=512, H=512, T=512, DECAY=0.8
//
// v10 — algebraic collapse + merged 128x128 GEMM tile:
//   bias>0 => y == 1 for all t (exact).  Only nh ~ 81 columns need compute.
//   convert_w_compact (scan fused in) -> g_nh, g_hidx, fp16 W splits
//   fused (grid 4096 = mt*8 + duty):
//     duty 0..3: GEMM n-tile n0=duty*128 (exit if n0>=nh) — 128x128 CTA tile,
//                A-convert fused, X loaded/split ONCE per chunk (was 2x)
//     duty 4..7: 32-row slice of the out:=1.0 fill (interleaved, hides in
//                the GEMM's idle DRAM headroom)
//   recur_kernel: separate high-occupancy kernel (~1 wave post-collapse)

typedef unsigned long long ull;

__device__ float  g_xw[33554432];               // 65536 x 512 fp32 (compacted cols)
__device__ __half g_b0[262144], g_b1[262144];   // 512 x 512 fp16 splits (compacted)
__device__ int    g_nh;                         // # columns with !(bias>0)
__device__ int    g_hidx[512];                  // compacted j -> h

// ---------------------------------------------------------------- helpers ---
__device__ __forceinline__ uint32_t smem_u32(const void* p) {
    uint32_t a;
    asm("{ .reg .u64 t; cvta.to.shared.u64 t, %1; cvt.u32.u64 %0, t; }"
        : "=r"(a) : "l"(p));
    return a;
}
__device__ __forceinline__ void cp16(uint32_t dst, const void* src) {
    asm volatile("cp.async.cg.shared.global [%0], [%1], 16;"
                 :: "r"(dst), "l"(src) : "memory");
}
__device__ __forceinline__ void ldsm4(uint32_t a, uint32_t& r0, uint32_t& r1,
                                      uint32_t& r2, uint32_t& r3) {
    asm volatile("ldmatrix.sync.aligned.m8n8.x4.shared.b16 {%0,%1,%2,%3}, [%4];"
                 : "=r"(r0), "=r"(r1), "=r"(r2), "=r"(r3) : "r"(a));
}
__device__ __forceinline__ void mma16816(float* d, const uint32_t* a,
                                         uint32_t b0, uint32_t b1) {
    asm volatile(
        "mma.sync.aligned.m16n8k16.row.col.f32.f16.f16.f32 "
        "{%0,%1,%2,%3}, {%4,%5,%6,%7}, {%8,%9}, {%0,%1,%2,%3};"
        : "+f"(d[0]), "+f"(d[1]), "+f"(d[2]), "+f"(d[3])
        : "r"(a[0]), "r"(a[1]), "r"(a[2]), "r"(a[3]), "r"(b0), "r"(b1));
}
__device__ __forceinline__ void mma16816h(uint32_t* d, const uint32_t* a,
                                          uint32_t b0, uint32_t b1) {
    asm volatile(
        "mma.sync.aligned.m16n8k16.row.col.f16.f16.f16.f16 "
        "{%0,%1}, {%2,%3,%4,%5}, {%6,%7}, {%0,%1};"
        : "+r"(d[0]), "+r"(d[1])
        : "r"(a[0]), "r"(a[1]), "r"(a[2]), "r"(a[3]), "r"(b0), "r"(b1));
}
__device__ __forceinline__ void split_pair(float ve, float vo,
                                           uint32_t& r0, uint32_t& r1) {
    __half2 h = __floats2half2_rn(ve, vo);
    float2  w = __half22float2(h);
    __half2 g = __floats2half2_rn(ve - w.x, vo - w.y);
    r0 = *(uint32_t*)&h;
    r1 = *(uint32_t*)&g;
}

// -------------------------------------------- convert_w_compact (+ scan) ---
// 512 threads.  Every CTA recomputes the bias scan locally (cheap); CTA 0
// publishes g_nh / g_hidx.  CTA j gathers W[:, hidx[j]] and fp16-splits it.
__global__ __launch_bounds__(512) void convert_w_compact(
    const float* __restrict__ W, const float* __restrict__ bias)
{
    const int tid = threadIdx.x;              // == h
    const int j   = blockIdx.x;               // 0..511
    __shared__ int wcnt[16], woff[16], lhidx[512], snh;

    bool p = !(bias[tid] > 0.0f);
    unsigned m = __ballot_sync(0xffffffffu, p);
    int lane = tid & 31, wid = tid >> 5;
    if (lane == 0) wcnt[wid] = __popc(m);
    __syncthreads();
    if (tid == 0) {
        int s = 0;
        for (int w = 0; w < 16; w++) { woff[w] = s; s += wcnt[w]; }
        snh = s;
        if (j == 0) g_nh = s;
    }
    __syncthreads();
    if (p) {
        int idx = woff[wid] + __popc(m & ((1u << lane) - 1u));
        lhidx[idx] = tid;
        if (j == 0) g_hidx[idx] = tid;
    }
    __syncthreads();

    const int nh = snh;
    if (j < nh) {
        const int h = lhidx[j];
        float v = W[(size_t)tid * 512 + h];
        __half h0 = __float2half_rn(v);
        g_b0[j * 512 + tid] = h0;
        g_b1[j * 512 + tid] = __float2half_rn(v - __half2float(h0));
    } else {
        g_b0[j * 512 + tid] = __ushort_as_half(0);
        g_b1[j * 512 + tid] = __ushort_as_half(0);
    }
}

// ----------------------------------------------------------- fused kernel ---
// GEMM: CTA 128(M) x 128(N) x 32(K-chunk), 256 thr = 8 warps (4m x 2n),
// warp tile 32x64.  4-stage cp.async.  X loaded+split ONCE per chunk.
// Stage (37376 B): X fp32 32x132 (16896) + b0 128x40h (10240) + b1 (10240).
#define STG    37376
#define XPITCH 132

__global__ __launch_bounds__(256, 1) void fused_kernel(
    const float* __restrict__ x, const float* __restrict__ bias,
    float* __restrict__ out)
{
    extern __shared__ char smraw[];
    const uint32_t smb = smem_u32(smraw);
    const int tid  = threadIdx.x;
    const int nh   = g_nh;
    const int mt   = blockIdx.x >> 3;         // m-tile 0..511 (batch-major)
    const int duty = blockIdx.x & 7;

    if (duty >= 4) {
        // ================= fill duty: 32 rows of out := 1.0 ===============
        const int fid = mt * 4 + (duty - 4);           // 0..2047
        const int r0 = fid * 32;
        const float4 one = make_float4(1.f, 1.f, 1.f, 1.f);
        #pragma unroll 4
        for (int rr = 0; rr < 32; rr += 2) {
            int r = r0 + rr + (tid >> 7);
            if (bias[r & 511] > 0.0f)
                ((float4*)(out + (size_t)r * 512))[tid & 127] = one;
        }
        return;
    }

    const int n0 = duty * 128;
    if (n0 >= nh) return;                     // compacted-N early exit

    // ======================= GEMM CTA =====================================
    const int b    = mt >> 2;
    const int t0   = (mt & 3) * 128;
    const int wid  = tid >> 5, lane = tid & 31;
    const int mw   = (wid >> 1) * 32;
    const int nw   = (wid & 1) * 64;

    const float* xb = x + (size_t)b * 262144 + t0;   // + k*512 + t

    float acc[2][8][4];
    uint32_t accc[2][8][2];
    #pragma unroll
    for (int i = 0; i < 2; i++)
        #pragma unroll
        for (int j = 0; j < 8; j++) {
            #pragma unroll
            for (int q = 0; q < 4; q++) acc[i][j][q] = 0.0f;
            accc[i][j][0] = 0u; accc[i][j][1] = 0u;
        }

    // X: 4 cp16/thread; B: 2 cp16/thread per split (128 rows x 4 chunks)
    #define LOAD_CHUNK(c, slot) do {                                          \
        int _k0 = (c) << 5;                                                   \
        uint32_t _sb = smb + (slot) * STG;                                    \
        _Pragma("unroll")                                                     \
        for (int _q = 0; _q < 4; _q++) {                                      \
            int _e = tid + 256 * _q;                                          \
            int _r = _e >> 5, _c = _e & 31;                                   \
            cp16(_sb + _r * (XPITCH * 4) + _c * 16,                           \
                 xb + (size_t)(_k0 + _r) * 512 + _c * 4);                     \
        }                                                                     \
        _Pragma("unroll")                                                     \
        for (int _q = 0; _q < 2; _q++) {                                      \
            int _e = tid + 256 * _q;                                          \
            int _r = _e >> 2, _c4 = _e & 3;                                   \
            cp16(_sb + 16896 + _r * 80 + _c4 * 16,                            \
                 g_b0 + (size_t)(n0 + _r) * 512 + _k0 + _c4 * 8);             \
            cp16(_sb + 27136 + _r * 80 + _c4 * 16,                            \
                 g_b1 + (size_t)(n0 + _r) * 512 + _k0 + _c4 * 8);             \
        }                                                                     \
    } while (0)

    LOAD_CHUNK(0, 0); asm volatile("cp.async.commit_group;" ::: "memory");
    LOAD_CHUNK(1, 1); asm volatile("cp.async.commit_group;" ::: "memory");
    LOAD_CHUNK(2, 2); asm volatile("cp.async.commit_group;" ::: "memory");

    for (int i = 0; i < 16; i++) {
        asm volatile("cp.async.wait_group 2;" ::: "memory");
        __syncthreads();
        if (i + 3 < 16) LOAD_CHUNK(i + 3, (i + 3) & 3);
        asm volatile("cp.async.commit_group;" ::: "memory");

        const int slot = i & 3;
        const float* Xs = (const float*)(smraw + slot * STG);
        const uint32_t bbase = smb + slot * STG + 16896;

        // ---- build A fragments ONCE (shared by the whole 128-wide N) ----
        uint32_t ar0[2][2][4], ar1[2][2][4];
        #pragma unroll
        for (int mi = 0; mi < 2; mi++) {
            #pragma unroll
            for (int ks = 0; ks < 2; ks++) {
                const int tq = mw + mi * 16 + (lane >> 2);
                const int kq = ks * 16 + (lane & 3) * 2;
                const float* p = Xs + kq * XPITCH + tq;
                split_pair(p[0],              p[XPITCH],
                           ar0[mi][ks][0], ar1[mi][ks][0]);
                split_pair(p[8],              p[XPITCH + 8],
                           ar0[mi][ks][1], ar1[mi][ks][1]);
                split_pair(p[8 * XPITCH],     p[9 * XPITCH],
                           ar0[mi][ks][2], ar1[mi][ks][2]);
                split_pair(p[8 * XPITCH + 8], p[9 * XPITCH + 8],
                           ar0[mi][ks][3], ar1[mi][ks][3]);
            }
        }

        #pragma unroll
        for (int ks = 0; ks < 2; ks++) {
            const int col = ks * 16 + (lane >> 4) * 8;
            uint32_t br0[4][4], br1[4][4];
            #pragma unroll
            for (int nb = 0; nb < 4; nb++) {
                int row = nw + nb * 16 + (lane & 15);
                ldsm4(bbase + (row * 40 + col) * 2,
                      br0[nb][0], br0[nb][1], br0[nb][2], br0[nb][3]);
                ldsm4(bbase + 10240 + (row * 40 + col) * 2,
                      br1[nb][0], br1[nb][1], br1[nb][2], br1[nb][3]);
            }
            #pragma unroll
            for (int mi = 0; mi < 2; mi++)
                #pragma unroll
                for (int nf = 0; nf < 8; nf++) {
                    int nb = nf >> 1, hh = nf & 1;
                    mma16816(acc[mi][nf],   ar0[mi][ks], br0[nb][hh], br0[nb][hh + 2]);
                    mma16816h(accc[mi][nf], ar0[mi][ks], br1[nb][hh], br1[nb][hh + 2]);
                    mma16816h(accc[mi][nf], ar1[mi][ks], br0[nb][hh], br0[nb][hh + 2]);
                }
        }
    }

    // epilogue: frag map m = lane/4 (+8), n = 2*(lane%4) (+1)
    #pragma unroll
    for (int mi = 0; mi < 2; mi++) {
        int row = mt * 128 + mw + mi * 16 + (lane >> 2);
        #pragma unroll
        for (int nf = 0; nf < 8; nf++) {
            int col = n0 + nw + nf * 8 + ((lane & 3) << 1);
            float2 c01 = __half22float2(*(__half2*)&accc[mi][nf][0]);
            float2 c23 = __half22float2(*(__half2*)&accc[mi][nf][1]);
            *(float2*)(g_xw + (size_t)row * 512 + col) =
                make_float2(acc[mi][nf][0] + c01.x, acc[mi][nf][1] + c01.y);
            *(float2*)(g_xw + (size_t)(row + 8) * 512 + col) =
                make_float2(acc[mi][nf][2] + c23.x, acc[mi][nf][3] + c23.y);
        }
    }
}

// ---------------------------------------------------------------- recurrence ---
// Separate high-occupancy kernel (post-collapse: ~1 wave active).
__global__ __launch_bounds__(128) void recur_kernel(
    const float* __restrict__ bias, float* __restrict__ out)
{
    const int nh = g_nh;
    const int b  = blockIdx.x >> 2;
    const int jt = blockIdx.x & 3;
    if (jt * 128 >= nh) return;

    extern __shared__ float dyn[];
    float* smin = dyn;                               // [2][32*128]
    float (*buf)[33] = (float(*)[33])(dyn + 8192);   // [128][33]
    __shared__ int sh_h[128];

    const int tid = threadIdx.x;
    const int j   = jt * 128 + tid;
    const bool valid = j < nh;
    const int h = valid ? g_hidx[j] : 0;
    sh_h[tid] = h;
    const float bb = valid ? bias[h] : 0.0f;

    float hs = 0.0f, y = 0.0f;

    const float* gx = g_xw + (size_t)b * 262144 + jt * 128;
    float*       po = out + (size_t)b * 262144;

    const uint32_t smin_u = smem_u32(smin);
    const int lrow = tid >> 2;
    const int lq   = (tid & 3) * 32;

    #define RLOAD(tc0, bsel) do {                                             \
        const float* _src = gx + (size_t)((tc0) + lrow) * 512 + lq;           \
        uint32_t _dst = smin_u + (((bsel) * 4096 + lrow * 128 + lq) * 4);     \
        cp16(_dst,      _src);      cp16(_dst + 16, _src + 4);                \
        cp16(_dst + 32, _src + 8);  cp16(_dst + 48, _src + 12);               \
        cp16(_dst + 64, _src + 16); cp16(_dst + 80, _src + 20);               \
        cp16(_dst + 96, _src + 24); cp16(_dst + 112, _src + 28);              \
    } while (0)

    RLOAD(0, 0);
    asm volatile("cp.async.commit_group;" ::: "memory");

    for (int tc = 0; tc < 16; tc++) {
        if (tc < 15) {
            RLOAD((tc + 1) * 32, (tc + 1) & 1);
            asm volatile("cp.async.commit_group;" ::: "memory");
            asm volatile("cp.async.wait_group 1;" ::: "memory");
        } else {
            asm volatile("cp.async.wait_group 0;" ::: "memory");
        }
        __syncthreads();

        const float* cs = smin + (tc & 1) * 4096;
        #pragma unroll
        for (int jj = 0; jj < 32; jj++) {
            float v = cs[jj * 128 + tid];
            hs = fmaxf(v + 0.8f * hs * (1.0f - y), 0.0f);
            y  = (hs + bb > 0.0f) ? 1.0f : 0.0f;
            buf[tid][jj] = y;
        }
        __syncthreads();
        const int r = tid >> 5;
        const int c = tid & 31;
        #pragma unroll
        for (int rr = 0; rr < 128; rr += 4) {
            int jrow = rr + r;
            if (jt * 128 + jrow < nh)
                po[(size_t)sh_h[jrow] * 512 + tc * 32 + c] = buf[jrow][c];
        }
        __syncthreads();
    }
}

// ------------------------------------------------------------------- launch ---
extern "C" void kernel_launch(void* const* d_in, const int* in_sizes, int n_in,
                              void* d_out, int out_size)
{
    const float* x = (const float*)d_in[0];   // (128, 512, 512)
    const float* W = (const float*)d_in[1];   // (512, 512)
    const float* b = (const float*)d_in[2];   // (1, 512)
    float* out = (float*)d_out;               // (128, 512, 512) float32

    cudaFuncSetAttribute(fused_kernel,
                         cudaFuncAttributeMaxDynamicSharedMemorySize, 4 * STG);
    cudaFuncSetAttribute(recur_kernel,
                         cudaFuncAttributeMaxDynamicSharedMemorySize, 49664);

    convert_w_compact<<<512, 512>>>(W, b);
    fused_kernel<<<4096, 256, 4 * STG>>>(x, b, out);
    recur_kernel<<<512, 128, 49664>>>(b, out);
}

// round 17
// speedup vs baseline: 1.2654x; 1.2654x over previous
#include <cuda_runtime.h>
#include <cuda_fp16.h>
#include <stdint.h>

// SNU on GB300 (base sm_103 ISA — mma.sync HMMA path):
//   out[b,h,t] = spike recurrence over xw[t,b,h] = sum_i x[b,i,t]*W[i,h]
//   B=128, I=512, H=512, T=512, DECAY=0.8
//
// v11 = v9 (153.7us proven) + merged scan/convert + fragment-level
//       N-predication in the GEMM (skip 8-col fragments >= nh; with nh~81
//       the n0=64 tile does 3/8 of its fragment work).
//   bias>0 => y == 1 for all t (exact).  Only nh ~ 81 columns need compute.

typedef unsigned long long ull;

__device__ float  g_xw[33554432];               // 65536 x 512 fp32 (compacted cols)
__device__ __half g_b0[262144], g_b1[262144];   // 512 x 512 fp16 splits (compacted)
__device__ int    g_nh;                         // # columns with !(bias>0)
__device__ int    g_hidx[512];                  // compacted j -> h
__device__ int    g_bflag[128];                 // per-batch producer counters

// ---------------------------------------------------------------- helpers ---
__device__ __forceinline__ uint32_t smem_u32(const void* p) {
    uint32_t a;
    asm("{ .reg .u64 t; cvta.to.shared.u64 t, %1; cvt.u32.u64 %0, t; }"
        : "=r"(a) : "l"(p));
    return a;
}
__device__ __forceinline__ void cp16(uint32_t dst, const void* src) {
    asm volatile("cp.async.cg.shared.global [%0], [%1], 16;"
                 :: "r"(dst), "l"(src) : "memory");
}
__device__ __forceinline__ void ldsm4(uint32_t a, uint32_t& r0, uint32_t& r1,
                                      uint32_t& r2, uint32_t& r3) {
    asm volatile("ldmatrix.sync.aligned.m8n8.x4.shared.b16 {%0,%1,%2,%3}, [%4];"
                 : "=r"(r0), "=r"(r1), "=r"(r2), "=r"(r3) : "r"(a));
}
__device__ __forceinline__ void mma16816(float* d, const uint32_t* a,
                                         uint32_t b0, uint32_t b1) {
    asm volatile(
        "mma.sync.aligned.m16n8k16.row.col.f32.f16.f16.f32 "
        "{%0,%1,%2,%3}, {%4,%5,%6,%7}, {%8,%9}, {%0,%1,%2,%3};"
        : "+f"(d[0]), "+f"(d[1]), "+f"(d[2]), "+f"(d[3])
        : "r"(a[0]), "r"(a[1]), "r"(a[2]), "r"(a[3]), "r"(b0), "r"(b1));
}
__device__ __forceinline__ void mma16816h(uint32_t* d, const uint32_t* a,
                                          uint32_t b0, uint32_t b1) {
    asm volatile(
        "mma.sync.aligned.m16n8k16.row.col.f16.f16.f16.f16 "
        "{%0,%1}, {%2,%3,%4,%5}, {%6,%7}, {%0,%1};"
        : "+r"(d[0]), "+r"(d[1])
        : "r"(a[0]), "r"(a[1]), "r"(a[2]), "r"(a[3]), "r"(b0), "r"(b1));
}
__device__ __forceinline__ void split_pair(float ve, float vo,
                                           uint32_t& r0, uint32_t& r1) {
    __half2 h = __floats2half2_rn(ve, vo);
    float2  w = __half22float2(h);
    __half2 g = __floats2half2_rn(ve - w.x, vo - w.y);
    r0 = *(uint32_t*)&h;
    r1 = *(uint32_t*)&g;
}

// -------------------------------------------- convert_w_compact (+ scan) ---
// 512 threads.  Every CTA recomputes the bias scan locally; CTA 0 publishes
// g_nh / g_hidx and resets the producer flags.  CTA j gathers W[:, hidx[j]].
__global__ __launch_bounds__(512) void convert_w_compact(
    const float* __restrict__ W, const float* __restrict__ bias)
{
    const int tid = threadIdx.x;              // == h
    const int j   = blockIdx.x;               // 0..511
    __shared__ int wcnt[16], woff[16], lhidx[512], snh;

    if (j == 0 && tid < 128) g_bflag[tid] = 0;

    bool p = !(bias[tid] > 0.0f);
    unsigned m = __ballot_sync(0xffffffffu, p);
    int lane = tid & 31, wid = tid >> 5;
    if (lane == 0) wcnt[wid] = __popc(m);
    __syncthreads();
    if (tid == 0) {
        int s = 0;
        for (int w = 0; w < 16; w++) { woff[w] = s; s += wcnt[w]; }
        snh = s;
        if (j == 0) g_nh = s;
    }
    __syncthreads();
    if (p) {
        int idx = woff[wid] + __popc(m & ((1u << lane) - 1u));
        lhidx[idx] = tid;
        if (j == 0) g_hidx[idx] = tid;
    }
    __syncthreads();

    const int nh = snh;
    if (j < nh) {
        const int h = lhidx[j];
        float v = W[(size_t)tid * 512 + h];
        __half h0 = __float2half_rn(v);
        g_b0[j * 512 + tid] = h0;
        g_b1[j * 512 + tid] = __float2half_rn(v - __half2float(h0));
    } else {
        g_b0[j * 512 + tid] = __ushort_as_half(0);
        g_b1[j * 512 + tid] = __ushort_as_half(0);
    }
}

// ----------------------------------------------------------- fused kernel ---
#define STG    27136
#define XPITCH 132
#define NGEMM  4096

__global__ __launch_bounds__(256, 2) void fused_kernel(
    const float* __restrict__ x, const float* __restrict__ bias,
    float* __restrict__ out)
{
    extern __shared__ char smraw[];
    const uint32_t smb = smem_u32(smraw);
    const int tid = threadIdx.x;
    const int nh  = g_nh;

    if (blockIdx.x < NGEMM) {
        const int bid   = blockIdx.x;
        const int mt    = bid >> 3;           // m-tile 0..511 (batch-major)
        const int n_idx = bid & 7;
        const int n0    = n_idx * 64;

        if (n0 < nh) {
            // ================= GEMM CTA (round-13 body + N-predication) ===
            const int b    = mt >> 2;
            const int t0   = (mt & 3) * 128;
            const int wid  = tid >> 5, lane = tid & 31;
            const int mw   = (wid >> 1) * 32;
            const int nw   = (wid & 1) * 32;

            // warp-uniform fragment activity masks
            const bool nbon[2] = { n0 + nw      < nh,        // cols nw+ 0..15
                                   n0 + nw + 16 < nh };      // cols nw+16..31
            const bool nfon[4] = { n0 + nw      < nh, n0 + nw +  8 < nh,
                                   n0 + nw + 16 < nh, n0 + nw + 24 < nh };

            const float* xb = x + (size_t)b * 262144 + t0;

            float acc[2][4][4];
            uint32_t accc[2][4][2];
            #pragma unroll
            for (int i = 0; i < 2; i++)
                #pragma unroll
                for (int j = 0; j < 4; j++) {
                    #pragma unroll
                    for (int q = 0; q < 4; q++) acc[i][j][q] = 0.0f;
                    accc[i][j][0] = 0u; accc[i][j][1] = 0u;
                }

            #define LOAD_CHUNK(c, slot) do {                                  \
                int _k0 = (c) << 5;                                           \
                uint32_t _sb = smb + (slot) * STG;                            \
                _Pragma("unroll")                                             \
                for (int _q = 0; _q < 4; _q++) {                              \
                    int _e = tid + 256 * _q;                                  \
                    int _r = _e >> 5, _c = _e & 31;                           \
                    cp16(_sb + _r * (XPITCH * 4) + _c * 16,                   \
                         xb + (size_t)(_k0 + _r) * 512 + _c * 4);             \
                }                                                             \
                {                                                             \
                    int _r = tid >> 2, _c4 = tid & 3;                         \
                    cp16(_sb + 16896 + _r * 80 + _c4 * 16,                    \
                         g_b0 + (size_t)(n0 + _r) * 512 + _k0 + _c4 * 8);     \
                    cp16(_sb + 22016 + _r * 80 + _c4 * 16,                    \
                         g_b1 + (size_t)(n0 + _r) * 512 + _k0 + _c4 * 8);     \
                }                                                             \
            } while (0)

            LOAD_CHUNK(0, 0); asm volatile("cp.async.commit_group;" ::: "memory");
            LOAD_CHUNK(1, 1); asm volatile("cp.async.commit_group;" ::: "memory");
            LOAD_CHUNK(2, 2); asm volatile("cp.async.commit_group;" ::: "memory");

            for (int i = 0; i < 16; i++) {
                asm volatile("cp.async.wait_group 2;" ::: "memory");
                __syncthreads();
                if (i + 3 < 16) LOAD_CHUNK(i + 3, (i + 3) & 3);
                asm volatile("cp.async.commit_group;" ::: "memory");

                const int slot = i & 3;
                const float* Xs = (const float*)(smraw + slot * STG);
                const uint32_t bbase = smb + slot * STG + 16896;

                uint32_t ar0[2][2][4], ar1[2][2][4];
                #pragma unroll
                for (int mi = 0; mi < 2; mi++) {
                    #pragma unroll
                    for (int ks = 0; ks < 2; ks++) {
                        const int tq = mw + mi * 16 + (lane >> 2);
                        const int kq = ks * 16 + (lane & 3) * 2;
                        const float* p = Xs + kq * XPITCH + tq;
                        split_pair(p[0],              p[XPITCH],
                                   ar0[mi][ks][0], ar1[mi][ks][0]);
                        split_pair(p[8],              p[XPITCH + 8],
                                   ar0[mi][ks][1], ar1[mi][ks][1]);
                        split_pair(p[8 * XPITCH],     p[9 * XPITCH],
                                   ar0[mi][ks][2], ar1[mi][ks][2]);
                        split_pair(p[8 * XPITCH + 8], p[9 * XPITCH + 8],
                                   ar0[mi][ks][3], ar1[mi][ks][3]);
                    }
                }

                #pragma unroll
                for (int ks = 0; ks < 2; ks++) {
                    const int col = ks * 16 + (lane >> 4) * 8;
                    uint32_t br0[2][4], br1[2][4];
                    #pragma unroll
                    for (int nb = 0; nb < 2; nb++) {
                        if (!nbon[nb]) continue;              // warp-uniform
                        int row = nw + nb * 16 + (lane & 15);
                        ldsm4(bbase + (row * 40 + col) * 2,
                              br0[nb][0], br0[nb][1], br0[nb][2], br0[nb][3]);
                        ldsm4(bbase + 5120 + (row * 40 + col) * 2,
                              br1[nb][0], br1[nb][1], br1[nb][2], br1[nb][3]);
                    }
                    #pragma unroll
                    for (int mi = 0; mi < 2; mi++)
                        #pragma unroll
                        for (int nf = 0; nf < 4; nf++) {
                            if (!nfon[nf]) continue;          // warp-uniform
                            int nb = nf >> 1, hh = nf & 1;
                            mma16816(acc[mi][nf],   ar0[mi][ks], br0[nb][hh], br0[nb][hh + 2]);
                            mma16816h(accc[mi][nf], ar0[mi][ks], br1[nb][hh], br1[nb][hh + 2]);
                            mma16816h(accc[mi][nf], ar1[mi][ks], br0[nb][hh], br0[nb][hh + 2]);
                        }
                }
            }

            #pragma unroll
            for (int mi = 0; mi < 2; mi++) {
                int row = mt * 128 + mw + mi * 16 + (lane >> 2);
                #pragma unroll
                for (int nf = 0; nf < 4; nf++) {
                    int col = n0 + nw + nf * 8 + ((lane & 3) << 1);
                    float2 c01 = __half22float2(*(__half2*)&accc[mi][nf][0]);
                    float2 c23 = __half22float2(*(__half2*)&accc[mi][nf][1]);
                    *(float2*)(g_xw + (size_t)row * 512 + col) =
                        make_float2(acc[mi][nf][0] + c01.x, acc[mi][nf][1] + c01.y);
                    *(float2*)(g_xw + (size_t)(row + 8) * 512 + col) =
                        make_float2(acc[mi][nf][2] + c23.x, acc[mi][nf][3] + c23.y);
                }
            }

            __threadfence();
            __syncthreads();
            if (tid == 0) atomicAdd(&g_bflag[mt >> 2], 1);
        }

        if (n_idx >= 2) {
            // ================= fill duty: 22 rows of out := 1.0 ===========
            const int fid = mt * 6 + (n_idx - 2);          // 0..3071
            const int r0 = fid * 22;
            const int r1 = (r0 + 22 < 65536) ? r0 + 22 : 65536;
            const float4 one = make_float4(1.f, 1.f, 1.f, 1.f);
            for (int rr = r0; rr < r1; rr += 2) {
                int r = rr + (tid >> 7);
                if (r < r1 && bias[r & 511] > 0.0f)
                    ((float4*)(out + (size_t)r * 512))[tid & 127] = one;
            }
        }

    } else {
        // ===================== recur CTA (v2, 256-thread) =================
        const int rid = blockIdx.x - NGEMM;   // 0..511
        const int b   = rid >> 2;
        const int jt  = rid & 3;
        if (jt * 128 >= nh) return;

        const int nt = (nh + 63) >> 6;        // active n-tiles
        const int target = nt * 4;            // producers per batch
        if (tid == 0) {
            while (atomicAdd(&g_bflag[b], 0) < target) __nanosleep(100);
        }
        __syncthreads();
        __threadfence();

        float* smin = (float*)smraw;                          // [2][32*128]
        float (*buf)[33] = (float(*)[33])(smraw + 32768);     // [128][33]
        __shared__ int sh_h[128];

        const int j = jt * 128 + (tid & 127);
        const bool valid = j < nh;
        if (tid < 128) sh_h[tid] = valid ? g_hidx[j] : 0;
        float bb = 0.0f, hs = 0.0f, y = 0.0f;
        if (tid < 128 && valid) bb = bias[g_hidx[j]];

        const float* gx = g_xw + (size_t)b * 262144 + jt * 128;
        float*       po = out + (size_t)b * 262144;

        const uint32_t smin_u = smem_u32(smin);
        const int lrow = tid >> 3;            // 0..31
        const int lq   = (tid & 7) * 16;

        #define RLOAD(tc0, bsel) do {                                         \
            const float* _src = gx + (size_t)((tc0) + lrow) * 512 + lq;       \
            uint32_t _dst = smin_u + (((bsel) * 4096 + lrow * 128 + lq) * 4); \
            cp16(_dst,      _src);      cp16(_dst + 16, _src + 4);            \
            cp16(_dst + 32, _src + 8);  cp16(_dst + 48, _src + 12);           \
        } while (0)

        RLOAD(0, 0);
        asm volatile("cp.async.commit_group;" ::: "memory");

        for (int tc = 0; tc < 16; tc++) {
            if (tc < 15) {
                RLOAD((tc + 1) * 32, (tc + 1) & 1);
                asm volatile("cp.async.commit_group;" ::: "memory");
                asm volatile("cp.async.wait_group 1;" ::: "memory");
            } else {
                asm volatile("cp.async.wait_group 0;" ::: "memory");
            }
            __syncthreads();

            const float* cs = smin + (tc & 1) * 4096;
            if (tid < 128) {
                #pragma unroll
                for (int jj = 0; jj < 32; jj++) {
                    float v = cs[jj * 128 + tid];
                    hs = fmaxf(v + 0.8f * hs * (1.0f - y), 0.0f);
                    y  = (hs + bb > 0.0f) ? 1.0f : 0.0f;
                    buf[tid][jj] = y;
                }
            }
            __syncthreads();
            const int r = tid >> 5;           // 0..7
            const int c = tid & 31;
            #pragma unroll
            for (int rr = 0; rr < 128; rr += 8) {
                int jrow = rr + r;
                if (jt * 128 + jrow < nh)
                    po[(size_t)sh_h[jrow] * 512 + tc * 32 + c] = buf[jrow][c];
            }
            __syncthreads();
        }
    }
}

// ------------------------------------------------------------------- launch ---
extern "C" void kernel_launch(void* const* d_in, const int* in_sizes, int n_in,
                              void* d_out, int out_size)
{
    const float* x = (const float*)d_in[0];   // (128, 512, 512)
    const float* W = (const float*)d_in[1];   // (512, 512)
    const float* b = (const float*)d_in[2];   // (1, 512)
    float* out = (float*)d_out;               // (128, 512, 512) float32

    cudaFuncSetAttribute(fused_kernel,
                         cudaFuncAttributeMaxDynamicSharedMemorySize, 4 * STG);

    convert_w_compact<<<512, 512>>>(W, b);
    fused_kernel<<<NGEMM + 512, 256, 4 * STG>>>(x, b, out);
}